// round 8
// baseline (speedup 1.0000x reference)
#include <cuda_runtime.h>

// Problem constants
#define NPIX   4096            // H*W
#define CH     32              // C/2
#define CIN    64              // C
#define BATCH  4
#define TM     64              // i-tile
#define TN     32              // j-tile
#define NSPLIT 32              // j-range splits across blocks (wave smoothing)
#define JCHUNK (NPIX / NSPLIT) // 128
#define NT     (JCHUNK / TN)   // 4 tiles per block
#define LOG2E  1.4426950408889634f

// smem plane sizes (floats). plane/4 mod 8 == 1 so the 4 batch planes land in
// rotated bank groups (strided cross-batch accesses become 4-phase optimal).
#define Q_PLANE 2052           // 32*64 + 4
#define K_PLANE 1028           // 32*32 + 4
#define V_PLANE 1028           // 32*32 + 4
#define P_ROW   68
// P rows spill up to 31*68 + 92 = 2200 floats (swizzle sl*4 + 64-wide row);
// 2212 >= 2200 and 2212/4 = 553 ≡ 1 mod 8 (keeps bank-group rotation).
#define P_PLANE 2212
#define SMEM_FLOATS (4 * (Q_PLANE + K_PLANE + V_PLANE + P_PLANE))  // 25280
#define SMEM_BYTES  (SMEM_FLOATS * 4)                              // 101120

// Scratch (static __device__ — no allocations allowed)
// g_cv[b][96][4096]: rows 0-31 = conv1 (Q, pre-scaled by log2e),
// 32-63 = conv2 (K), 64-95 = conv3 (V)
__device__ float g_cv[BATCH * 96 * NPIX];
// g_z[split][b][131072]: partial attention outputs, flat index i*32+c
__device__ float g_z[NSPLIT * BATCH * CH * NPIX];

// ---- packed f32x2 + fast-math helpers -------------------------------------
__device__ __forceinline__ unsigned long long bcast2(float v) {
    unsigned long long r;
    asm("mov.b64 %0, {%1, %1};" : "=l"(r) : "f"(v));
    return r;
}
__device__ __forceinline__ void unpack2(unsigned long long p, float& lo, float& hi) {
    asm("mov.b64 {%0, %1}, %2;" : "=f"(lo), "=f"(hi) : "l"(p));
}
__device__ __forceinline__ unsigned long long ffma2(unsigned long long a,
                                                    unsigned long long b,
                                                    unsigned long long c) {
    unsigned long long d;
    asm("fma.rn.f32x2 %0, %1, %2, %3;" : "=l"(d) : "l"(a), "l"(b), "l"(c));
    return d;
}
__device__ __forceinline__ float ex2_approx(float x) {
    float y;
    asm("ex2.approx.f32 %0, %1;" : "=f"(y) : "f"(x));
    return y;
}

// ---------------------------------------------------------------------------
// Kernel 1: fused 1x1 convs producing Q/K/V scratch (natural [b][ch][p] layout)
// grid (32, 4, 6), block 128. blockIdx.z picks 16 of the 96 output channels.
// Conv1 (Q) output pre-scaled by log2e so attn uses exp2 directly.
// ---------------------------------------------------------------------------
__global__ void __launch_bounds__(128) conv_qkv_kernel(
    const float* __restrict__ x,
    const float* __restrict__ w1, const float* __restrict__ b1,
    const float* __restrict__ w2, const float* __restrict__ b2,
    const float* __restrict__ w3, const float* __restrict__ b3)
{
    __shared__ float ws[64 * 16];   // [c][r] transposed weights for 16 channels
    __shared__ float bs[16];
    const int t = threadIdx.x;
    const int p = blockIdx.x * 128 + t;
    const int b = blockIdx.y;
    const int g = blockIdx.z;       // 0..5
    const float* w  = (g < 2) ? w1 : ((g < 4) ? w2 : w3);
    const float* bi = (g < 2) ? b1 : ((g < 4) ? b2 : b3);
    const int chb = (g & 1) * 16;

    if (t < 16) bs[t] = bi[chb + t];
    for (int idx = t; idx < 1024; idx += 128) {
        int r = idx >> 6, c = idx & 63;
        ws[c * 16 + r] = w[(chb + r) * 64 + c];
    }
    __syncthreads();

    float xr[64];
    const float* xp = x + b * CIN * NPIX + p;
#pragma unroll
    for (int c = 0; c < 64; c++) xr[c] = xp[c * NPIX];

    float acc[16];
#pragma unroll
    for (int r = 0; r < 16; r++) acc[r] = bs[r];
#pragma unroll
    for (int c = 0; c < 64; c++) {
#pragma unroll
        for (int r = 0; r < 16; r++)
            acc[r] = fmaf(xr[c], ws[c * 16 + r], acc[r]);
    }

    const float scale = (g < 2) ? LOG2E : 1.0f;   // fold softmax log2e into Q
    float* out = g_cv + b * 96 * NPIX + (g * 16) * NPIX + p;
#pragma unroll
    for (int r = 0; r < 16; r++) out[r * NPIX] = acc[r] * scale;
}

// ---------------------------------------------------------------------------
// Kernel 2: fused QK^T -> softmax over batch -> P@V, packed f32x2 math.
// grid (64, 32): blockIdx.x = i-tile (64 rows), blockIdx.y = j-split (128 cols,
// processed as 4 tiles of TN=32). block 256 threads = 8 warps, 2 blocks/SM.
// Warp w owns rows i in [8w, 8w+8). Lane l: b = l>>3, sl = l&7 (4-j subtile in
// QK, 4-c subtile in PV). Softmax across b = shfl.xor 8 / 16 within the warp.
// K/V tiles are prefetched into registers during the previous tile's compute
// so the L2 latency overlaps the FMA phase.
// ---------------------------------------------------------------------------
__global__ void __launch_bounds__(256, 2) attn_kernel()
{
    extern __shared__ float sm[];
    float* q_s = sm;                     // [4][32][64] + pad (layout [b][c][i])
    float* k_s = sm + 4 * Q_PLANE;       // [4][32][32] + pad (layout [b][c][j])
    float* v_s = k_s + 4 * K_PLANE;      // [4][32][32] + pad (layout [b][j][c])
    float* p_s = v_s + 4 * V_PLANE;      // [4][32][68(+swz)] (layout [b][j][i])

    const int tid = threadIdx.x;
    const int w   = tid >> 5;
    const int l   = tid & 31;
    const int b   = l >> 3;
    const int sl  = l & 7;
    const int i0  = blockIdx.x * TM;
    const int j0base = blockIdx.y * JCHUNK;

    // Per-thread K/V tile slice addressing (u = 0..3, idx = tid + 256u):
    // bb = idx>>8, rem = idx&255, row = rem>>3, f4 = (rem&7)*4
    const int bb0  = tid >> 8;           // 0 for u<... recompute per u below
    (void)bb0;

    // Load Q tile: Qflat[b][i*32+c] -> q_s[b][c][i] (transposed)
    for (int idx = tid; idx < 2048; idx += 256) {
        int b2 = idx >> 9, rem = idx & 511, i = rem >> 3, cq = rem & 7;
        const float4 v = *reinterpret_cast<const float4*>(
            g_cv + b2 * 96 * NPIX + (i0 + i) * 32 + cq * 4);
        float* qd = q_s + b2 * Q_PLANE + (cq * 4) * 64 + i;
        qd[0] = v.x; qd[64] = v.y; qd[128] = v.z; qd[192] = v.w;
    }

    // Prefetch registers + precomputed addresses for K/V tile slices
    float4 kreg[4], vreg[4];
    const float* kgp[4];   // K gmem base (add j0)
    const float* vgp[4];   // V gmem base (add j0*32)
    float* ksp[4];         // K smem dst
    float* vsp[4];         // V smem dst
#pragma unroll
    for (int u = 0; u < 4; u++) {
        int idx = tid + u * 256;
        int bbu = idx >> 8, rem = idx & 255;
        int row = rem >> 3, f4 = (rem & 7) * 4;
        kgp[u] = g_cv + bbu * 96 * NPIX + (32 + row) * NPIX + f4;
        vgp[u] = g_cv + bbu * 96 * NPIX + 64 * NPIX + row * 32 + f4;
        ksp[u] = k_s + bbu * K_PLANE + row * 32 + f4;
        vsp[u] = v_s + bbu * V_PLANE + row * 32 + f4;
    }
    // Prologue: prefetch tile 0
#pragma unroll
    for (int u = 0; u < 4; u++) {
        kreg[u] = *reinterpret_cast<const float4*>(kgp[u] + j0base);
        vreg[u] = *reinterpret_cast<const float4*>(vgp[u] + j0base * 32);
    }

    // acc packed along i: acc2[p][cc] halves = i = 2p, 2p+1
    unsigned long long acc2[4][4];
#pragma unroll
    for (int p = 0; p < 4; p++)
#pragma unroll
        for (int cc = 0; cc < 4; cc++) acc2[p][cc] = 0ull;

    for (int jt = 0; jt < NT; jt++) {
        __syncthreads();   // prior tile's k_s/v_s reads done (1st iter: Q ready)
        // Commit prefetched K/V registers to smem
#pragma unroll
        for (int u = 0; u < 4; u++) {
            *reinterpret_cast<float4*>(ksp[u]) = kreg[u];
            *reinterpret_cast<float4*>(vsp[u]) = vreg[u];
        }
        __syncthreads();

        // Prefetch next tile's K/V (LDG latency overlaps the compute below)
        if (jt + 1 < NT) {
            const int j0n = j0base + (jt + 1) * TN;
#pragma unroll
            for (int u = 0; u < 4; u++) {
                kreg[u] = *reinterpret_cast<const float4*>(kgp[u] + j0n);
                vreg[u] = *reinterpret_cast<const float4*>(vgp[u] + j0n * 32);
            }
        }

        // ---- QK: s2[p][jj], packed pair over i = (2p, 2p+1), 4 j per lane ----
        unsigned long long s2[4][4];
#pragma unroll
        for (int p = 0; p < 4; p++)
#pragma unroll
            for (int jj = 0; jj < 4; jj++) s2[p][jj] = 0ull;

        const float* qb = q_s + b * Q_PLANE + w * 8;
        const float* kb = k_s + b * K_PLANE + sl * 4;
#pragma unroll 8
        for (int c = 0; c < 32; c++) {
            ulonglong2 qa = *reinterpret_cast<const ulonglong2*>(qb + c * 64);
            ulonglong2 qc = *reinterpret_cast<const ulonglong2*>(qb + c * 64 + 4);
            float4 ka = *reinterpret_cast<const float4*>(kb + c * 32);
            unsigned long long qq[4] = {qa.x, qa.y, qc.x, qc.y};
            float kk[4] = {ka.x, ka.y, ka.z, ka.w};
#pragma unroll
            for (int jj = 0; jj < 4; jj++) {
                unsigned long long kp = bcast2(kk[jj]);
#pragma unroll
                for (int p = 0; p < 4; p++)
                    s2[p][jj] = ffma2(qq[p], kp, s2[p][jj]);
            }
        }

        // ---- softmax across batch + P store, two i-halves ----
        // Q pre-scaled by log2e; |s| small enough that max-subtraction is
        // unnecessary (no overflow / no total underflow).
#pragma unroll
        for (int half = 0; half < 2; half++) {
            float sh[4][4];   // [i within half][jj]
#pragma unroll
            for (int p = 0; p < 2; p++)
#pragma unroll
                for (int jj = 0; jj < 4; jj++)
                    unpack2(s2[2 * half + p][jj], sh[2 * p][jj], sh[2 * p + 1][jj]);

#pragma unroll
            for (int ii = 0; ii < 4; ii++) {
#pragma unroll
                for (int jj = 0; jj < 4; jj++) {
                    float e = ex2_approx(sh[ii][jj]);
                    float z = e + __shfl_xor_sync(0xffffffffu, e, 8);
                    z = z + __shfl_xor_sync(0xffffffffu, z, 16);
                    sh[ii][jj] = __fdividef(e, z);
                }
            }

            // store P transposed: p_s[b][j][i] with +sl*4 bank swizzle
            float* pd = p_s + b * P_PLANE + w * 8 + half * 4 + sl * 4;
#pragma unroll
            for (int jj = 0; jj < 4; jj++)
                *reinterpret_cast<float4*>(pd + (sl * 4 + jj) * P_ROW) =
                    make_float4(sh[0][jj], sh[1][jj], sh[2][jj], sh[3][jj]);
        }
        __syncwarp();   // P tile is warp-private (warp reads only its 8 columns)

        // ---- PV: lane (b, sc=sl) accumulates acc2 over this tile's 32 j ----
        const float* pb = p_s + b * P_PLANE + w * 8;
        const float* vb = v_s + b * V_PLANE + sl * 4;
#pragma unroll 4
        for (int j = 0; j < TN; j++) {
            int off = j * P_ROW + ((j >> 2) << 2);   // undo +sl*4 swizzle
            ulonglong2 pva = *reinterpret_cast<const ulonglong2*>(pb + off);
            ulonglong2 pvb = *reinterpret_cast<const ulonglong2*>(pb + off + 4);
            float4 vv = *reinterpret_cast<const float4*>(vb + j * 32);
            unsigned long long pvq[4] = {pva.x, pva.y, pvb.x, pvb.y};
            unsigned long long vr[4] = {bcast2(vv.x), bcast2(vv.y),
                                        bcast2(vv.z), bcast2(vv.w)};
#pragma unroll
            for (int p = 0; p < 4; p++)
#pragma unroll
                for (int cc = 0; cc < 4; cc++)
                    acc2[p][cc] = ffma2(pvq[p], vr[cc], acc2[p][cc]);
        }
    }

    // Write partial z: g_z[split][b][(i)*32 + c]
    float* zo = g_z + (blockIdx.y * BATCH + b) * CH * NPIX + (i0 + w * 8) * 32 + sl * 4;
#pragma unroll
    for (int p = 0; p < 4; p++) {
        float lo[4], hi[4];
#pragma unroll
        for (int cc = 0; cc < 4; cc++) unpack2(acc2[p][cc], lo[cc], hi[cc]);
        *reinterpret_cast<float4*>(zo + (2 * p) * 32) =
            make_float4(lo[0], lo[1], lo[2], lo[3]);
        *reinterpret_cast<float4*>(zo + (2 * p + 1) * 32) =
            make_float4(hi[0], hi[1], hi[2], hi[3]);
    }
}

// ---------------------------------------------------------------------------
// Kernel 3: sum the NSPLIT partials + final 1x1 conv (w4,b4) -> d_out
// grid (64, 4), block 64 (256 blocks > 148 SMs for better chip fill).
// ---------------------------------------------------------------------------
__global__ void __launch_bounds__(64) conv_out_kernel(
    const float* __restrict__ w4,
    const float* __restrict__ b4,
    float* __restrict__ out)
{
    __shared__ float ws[2048];   // w4 [64][32] natural
    __shared__ float bsm[64];
    const int t = threadIdx.x;
    const int p = blockIdx.x * 64 + t;
    const int b = blockIdx.y;

    for (int idx = t; idx < 2048; idx += 64) ws[idx] = w4[idx];
    if (t < 64) bsm[t] = b4[t];
    __syncthreads();

    float zs[32];
#pragma unroll
    for (int ch = 0; ch < 32; ch++) zs[ch] = 0.f;
    for (int sp = 0; sp < NSPLIT; sp++) {
        const float* zp = g_z + (sp * BATCH + b) * CH * NPIX + p;
#pragma unroll
        for (int ch = 0; ch < 32; ch++) zs[ch] += zp[ch * NPIX];
    }

    float* op = out + b * 64 * NPIX + p;
#pragma unroll
    for (int o = 0; o < 64; o++) {
        float a = bsm[o];
#pragma unroll
        for (int ch = 0; ch < 32; ch++)
            a = fmaf(ws[o * 32 + ch], zs[ch], a);
        op[o * NPIX] = a;
    }
}

// ---------------------------------------------------------------------------
extern "C" void kernel_launch(void* const* d_in, const int* in_sizes, int n_in,
                              void* d_out, int out_size)
{
    (void)in_sizes; (void)n_in; (void)out_size;
    const float* x  = (const float*)d_in[0];
    const float* w1 = (const float*)d_in[1];
    const float* b1 = (const float*)d_in[2];
    const float* w2 = (const float*)d_in[3];
    const float* b2 = (const float*)d_in[4];
    const float* w3 = (const float*)d_in[5];
    const float* b3 = (const float*)d_in[6];
    const float* w4 = (const float*)d_in[7];
    const float* b4 = (const float*)d_in[8];
    float* out = (float*)d_out;

    // idempotent; needed for ~99 KB dynamic smem (first call outside capture)
    cudaFuncSetAttribute(attn_kernel, cudaFuncAttributeMaxDynamicSharedMemorySize,
                         SMEM_BYTES);

    conv_qkv_kernel<<<dim3(32, 4, 6), 128>>>(x, w1, b1, w2, b2, w3, b3);
    attn_kernel<<<dim3(NPIX / TM, NSPLIT), 256, SMEM_BYTES>>>();
    conv_out_kernel<<<dim3(64, 4), 64>>>(w4, b4, out);
}

// round 15
// speedup vs baseline: 1.2004x; 1.2004x over previous
#include <cuda_runtime.h>

// Problem constants
#define NPIX   4096            // H*W
#define CH     32              // C/2
#define CIN    64              // C
#define BATCH  4
#define TM     64              // i-tile
#define TN     32              // j-tile
#define NSPLIT 16              // j-range splits across blocks
#define JCHUNK (NPIX / NSPLIT) // 256
#define NT     (JCHUNK / TN)   // 8 tiles per block
#define LOG2E  1.4426950408889634f

// smem plane sizes (floats). plane/4 mod 8 == 1 so the 4 batch planes land in
// rotated bank groups (strided cross-batch accesses become 4-phase optimal).
#define Q_PLANE 2052           // 32*64 + 4
#define K_PLANE 1028           // 32*32 + 4
#define V_PLANE 1028           // 32*32 + 4
#define P_ROW   68
// P rows spill up to 31*68 + 92 = 2200 floats (swizzle sl*4 + 64-wide row);
// 2212 >= 2200 and 2212/4 = 553 ≡ 1 mod 8 (keeps bank-group rotation).
#define P_PLANE 2212
#define SMEM_FLOATS (4 * (Q_PLANE + K_PLANE + V_PLANE + P_PLANE))  // 25280
#define SMEM_BYTES  (SMEM_FLOATS * 4)                              // 101120

// Scratch (static __device__ — no allocations allowed)
// g_cv[b][96][4096]: rows 0-31 = conv1 (Q, pre-scaled by log2e),
// 32-63 = conv2 (K), 64-95 = conv3 (V)
__device__ float g_cv[BATCH * 96 * NPIX];
// g_z[split][b][131072]: partial attention outputs, flat index i*32+c
__device__ float g_z[NSPLIT * BATCH * CH * NPIX];

// ---- packed f32x2 + fast-math helpers -------------------------------------
__device__ __forceinline__ unsigned long long bcast2(float v) {
    unsigned long long r;
    asm("mov.b64 %0, {%1, %1};" : "=l"(r) : "f"(v));
    return r;
}
__device__ __forceinline__ void unpack2(unsigned long long p, float& lo, float& hi) {
    asm("mov.b64 {%0, %1}, %2;" : "=f"(lo), "=f"(hi) : "l"(p));
}
__device__ __forceinline__ unsigned long long ffma2(unsigned long long a,
                                                    unsigned long long b,
                                                    unsigned long long c) {
    unsigned long long d;
    asm("fma.rn.f32x2 %0, %1, %2, %3;" : "=l"(d) : "l"(a), "l"(b), "l"(c));
    return d;
}
__device__ __forceinline__ float ex2_approx(float x) {
    float y;
    asm("ex2.approx.f32 %0, %1;" : "=f"(y) : "f"(x));
    return y;
}

// ---------------------------------------------------------------------------
// Kernel 1: fused 1x1 convs producing Q/K/V scratch (natural [b][ch][p] layout)
// grid (32, 4, 6), block 128. blockIdx.z picks 16 of the 96 output channels.
// Conv1 (Q) output pre-scaled by log2e so attn uses exp2 directly.
// ---------------------------------------------------------------------------
__global__ void __launch_bounds__(128) conv_qkv_kernel(
    const float* __restrict__ x,
    const float* __restrict__ w1, const float* __restrict__ b1,
    const float* __restrict__ w2, const float* __restrict__ b2,
    const float* __restrict__ w3, const float* __restrict__ b3)
{
    __shared__ float ws[64 * 16];   // [c][r] transposed weights for 16 channels
    __shared__ float bs[16];
    const int t = threadIdx.x;
    const int p = blockIdx.x * 128 + t;
    const int b = blockIdx.y;
    const int g = blockIdx.z;       // 0..5
    const float* w  = (g < 2) ? w1 : ((g < 4) ? w2 : w3);
    const float* bi = (g < 2) ? b1 : ((g < 4) ? b2 : b3);
    const int chb = (g & 1) * 16;

    if (t < 16) bs[t] = bi[chb + t];
    for (int idx = t; idx < 1024; idx += 128) {
        int r = idx >> 6, c = idx & 63;
        ws[c * 16 + r] = w[(chb + r) * 64 + c];
    }
    __syncthreads();

    float xr[64];
    const float* xp = x + b * CIN * NPIX + p;
#pragma unroll
    for (int c = 0; c < 64; c++) xr[c] = xp[c * NPIX];

    float acc[16];
#pragma unroll
    for (int r = 0; r < 16; r++) acc[r] = bs[r];
#pragma unroll
    for (int c = 0; c < 64; c++) {
#pragma unroll
        for (int r = 0; r < 16; r++)
            acc[r] = fmaf(xr[c], ws[c * 16 + r], acc[r]);
    }

    const float scale = (g < 2) ? LOG2E : 1.0f;   // fold softmax log2e into Q
    float* out = g_cv + b * 96 * NPIX + (g * 16) * NPIX + p;
#pragma unroll
    for (int r = 0; r < 16; r++) out[r * NPIX] = acc[r] * scale;
}

// ---------------------------------------------------------------------------
// Kernel 2: fused QK^T -> softmax over batch -> P@V, packed f32x2 math.
// grid (64, 16): blockIdx.x = i-tile (64 rows), blockIdx.y = j-split (256 cols,
// processed as 8 tiles of TN=32). block 256 threads = 8 warps, 2 blocks/SM.
// Warp w owns rows i in [8w, 8w+8). Lane l: b = l>>3, sl = l&7 (4-j subtile in
// QK, 4-c subtile in PV). Softmax across b = shfl.xor 8 / 16 within the warp.
// K tiles are prefetched into registers during the previous tile's compute
// (register-lean: K only) so half the per-tile L2 latency is hidden.
// ---------------------------------------------------------------------------
__global__ void __launch_bounds__(256, 2) attn_kernel()
{
    extern __shared__ float sm[];
    float* q_s = sm;                     // [4][32][64] + pad (layout [b][c][i])
    float* k_s = sm + 4 * Q_PLANE;       // [4][32][32] + pad (layout [b][c][j])
    float* v_s = k_s + 4 * K_PLANE;      // [4][32][32] + pad (layout [b][j][c])
    float* p_s = v_s + 4 * V_PLANE;      // [4][32][68(+swz)] (layout [b][j][i])

    const int tid = threadIdx.x;
    const int w   = tid >> 5;
    const int l   = tid & 31;
    const int b   = l >> 3;
    const int sl  = l & 7;
    const int i0  = blockIdx.x * TM;
    const int j0base = blockIdx.y * JCHUNK;

    // Load Q tile: Qflat[b][i*32+c] -> q_s[b][c][i] (transposed)
    for (int idx = tid; idx < 2048; idx += 256) {
        int b2 = idx >> 9, rem = idx & 511, i = rem >> 3, cq = rem & 7;
        const float4 v = *reinterpret_cast<const float4*>(
            g_cv + b2 * 96 * NPIX + (i0 + i) * 32 + cq * 4);
        float* qd = q_s + b2 * Q_PLANE + (cq * 4) * 64 + i;
        qd[0] = v.x; qd[64] = v.y; qd[128] = v.z; qd[192] = v.w;
    }

    // K-tile register prefetch (slices u: idx = tid + 256u -> bb, row, f4)
    float4 kreg[4];
#pragma unroll
    for (int u = 0; u < 4; u++) {
        int idx = tid + u * 256;
        int bbu = idx >> 8, rem = idx & 255;
        int row = rem >> 3, f4 = (rem & 7) * 4;
        kreg[u] = *reinterpret_cast<const float4*>(
            g_cv + bbu * 96 * NPIX + (32 + row) * NPIX + j0base + f4);
    }

    // acc packed along i: acc2[p][cc] halves = i = 2p, 2p+1
    unsigned long long acc2[4][4];
#pragma unroll
    for (int p = 0; p < 4; p++)
#pragma unroll
        for (int cc = 0; cc < 4; cc++) acc2[p][cc] = 0ull;

    for (int jt = 0; jt < NT; jt++) {
        const int j0 = j0base + jt * TN;
        __syncthreads();   // prior tile's k_s/v_s reads done (1st iter: Q ready)

        // Commit prefetched K registers + copy V tile (LDG->STS, overlapped
        // across the 8 warps inside the commit window)
#pragma unroll
        for (int u = 0; u < 4; u++) {
            int idx = tid + u * 256;
            int bbu = idx >> 8, rem = idx & 255;
            int row = rem >> 3, f4 = (rem & 7) * 4;
            *reinterpret_cast<float4*>(k_s + bbu * K_PLANE + row * 32 + f4) =
                kreg[u];
            *reinterpret_cast<float4*>(v_s + bbu * V_PLANE + row * 32 + f4) =
                *reinterpret_cast<const float4*>(
                    g_cv + bbu * 96 * NPIX + 64 * NPIX + (j0 + row) * 32 + f4);
        }
        __syncthreads();

        // Prefetch next tile's K (LDG latency overlaps the compute below)
        if (jt + 1 < NT) {
            const int j0n = j0 + TN;
#pragma unroll
            for (int u = 0; u < 4; u++) {
                int idx = tid + u * 256;
                int bbu = idx >> 8, rem = idx & 255;
                int row = rem >> 3, f4 = (rem & 7) * 4;
                kreg[u] = *reinterpret_cast<const float4*>(
                    g_cv + bbu * 96 * NPIX + (32 + row) * NPIX + j0n + f4);
            }
        }

        // ---- QK: s2[p][jj], packed pair over i = (2p, 2p+1), 4 j per lane ----
        unsigned long long s2[4][4];
#pragma unroll
        for (int p = 0; p < 4; p++)
#pragma unroll
            for (int jj = 0; jj < 4; jj++) s2[p][jj] = 0ull;

        const float* qb = q_s + b * Q_PLANE + w * 8;
        const float* kb = k_s + b * K_PLANE + sl * 4;
#pragma unroll 8
        for (int c = 0; c < 32; c++) {
            ulonglong2 qa = *reinterpret_cast<const ulonglong2*>(qb + c * 64);
            ulonglong2 qc = *reinterpret_cast<const ulonglong2*>(qb + c * 64 + 4);
            float4 ka = *reinterpret_cast<const float4*>(kb + c * 32);
            unsigned long long qq[4] = {qa.x, qa.y, qc.x, qc.y};
            float kk[4] = {ka.x, ka.y, ka.z, ka.w};
#pragma unroll
            for (int jj = 0; jj < 4; jj++) {
                unsigned long long kp = bcast2(kk[jj]);
#pragma unroll
                for (int p = 0; p < 4; p++)
                    s2[p][jj] = ffma2(qq[p], kp, s2[p][jj]);
            }
        }

        // ---- softmax across batch + P store, two i-halves ----
        // Q pre-scaled by log2e; |s| small enough that max-subtraction is
        // unnecessary (no overflow / no total underflow).
#pragma unroll
        for (int half = 0; half < 2; half++) {
            float sh[4][4];   // [i within half][jj]
#pragma unroll
            for (int p = 0; p < 2; p++)
#pragma unroll
                for (int jj = 0; jj < 4; jj++)
                    unpack2(s2[2 * half + p][jj], sh[2 * p][jj], sh[2 * p + 1][jj]);

#pragma unroll
            for (int ii = 0; ii < 4; ii++) {
#pragma unroll
                for (int jj = 0; jj < 4; jj++) {
                    float e = ex2_approx(sh[ii][jj]);
                    float z = e + __shfl_xor_sync(0xffffffffu, e, 8);
                    z = z + __shfl_xor_sync(0xffffffffu, z, 16);
                    sh[ii][jj] = __fdividef(e, z);
                }
            }

            // store P transposed: p_s[b][j][i] with +sl*4 bank swizzle
            float* pd = p_s + b * P_PLANE + w * 8 + half * 4 + sl * 4;
#pragma unroll
            for (int jj = 0; jj < 4; jj++)
                *reinterpret_cast<float4*>(pd + (sl * 4 + jj) * P_ROW) =
                    make_float4(sh[0][jj], sh[1][jj], sh[2][jj], sh[3][jj]);
        }
        __syncwarp();   // P tile is warp-private (warp reads only its 8 columns)

        // ---- PV: lane (b, sc=sl) accumulates acc2 over this tile's 32 j ----
        const float* pb = p_s + b * P_PLANE + w * 8;
        const float* vb = v_s + b * V_PLANE + sl * 4;
#pragma unroll 4
        for (int j = 0; j < TN; j++) {
            int off = j * P_ROW + ((j >> 2) << 2);   // undo +sl*4 swizzle
            ulonglong2 pva = *reinterpret_cast<const ulonglong2*>(pb + off);
            ulonglong2 pvb = *reinterpret_cast<const ulonglong2*>(pb + off + 4);
            float4 vv = *reinterpret_cast<const float4*>(vb + j * 32);
            unsigned long long pvq[4] = {pva.x, pva.y, pvb.x, pvb.y};
            unsigned long long vr[4] = {bcast2(vv.x), bcast2(vv.y),
                                        bcast2(vv.z), bcast2(vv.w)};
#pragma unroll
            for (int p = 0; p < 4; p++)
#pragma unroll
                for (int cc = 0; cc < 4; cc++)
                    acc2[p][cc] = ffma2(pvq[p], vr[cc], acc2[p][cc]);
        }
    }

    // Write partial z: g_z[split][b][(i)*32 + c]
    float* zo = g_z + (blockIdx.y * BATCH + b) * CH * NPIX + (i0 + w * 8) * 32 + sl * 4;
#pragma unroll
    for (int p = 0; p < 4; p++) {
        float lo[4], hi[4];
#pragma unroll
        for (int cc = 0; cc < 4; cc++) unpack2(acc2[p][cc], lo[cc], hi[cc]);
        *reinterpret_cast<float4*>(zo + (2 * p) * 32) =
            make_float4(lo[0], lo[1], lo[2], lo[3]);
        *reinterpret_cast<float4*>(zo + (2 * p + 1) * 32) =
            make_float4(hi[0], hi[1], hi[2], hi[3]);
    }
}

// ---------------------------------------------------------------------------
// Kernel 3: sum the NSPLIT partials + final 1x1 conv (w4,b4) -> d_out
// grid (64, 4), block 64 (256 blocks > 148 SMs for better chip fill).
// ---------------------------------------------------------------------------
__global__ void __launch_bounds__(64) conv_out_kernel(
    const float* __restrict__ w4,
    const float* __restrict__ b4,
    float* __restrict__ out)
{
    __shared__ float ws[2048];   // w4 [64][32] natural
    __shared__ float bsm[64];
    const int t = threadIdx.x;
    const int p = blockIdx.x * 64 + t;
    const int b = blockIdx.y;

    for (int idx = t; idx < 2048; idx += 64) ws[idx] = w4[idx];
    if (t < 64) bsm[t] = b4[t];
    __syncthreads();

    float zs[32];
#pragma unroll
    for (int ch = 0; ch < 32; ch++) zs[ch] = 0.f;
    for (int sp = 0; sp < NSPLIT; sp++) {
        const float* zp = g_z + (sp * BATCH + b) * CH * NPIX + p;
#pragma unroll
        for (int ch = 0; ch < 32; ch++) zs[ch] += zp[ch * NPIX];
    }

    float* op = out + b * 64 * NPIX + p;
#pragma unroll
    for (int o = 0; o < 64; o++) {
        float a = bsm[o];
#pragma unroll
        for (int ch = 0; ch < 32; ch++)
            a = fmaf(ws[o * 32 + ch], zs[ch], a);
        op[o * NPIX] = a;
    }
}

// ---------------------------------------------------------------------------
extern "C" void kernel_launch(void* const* d_in, const int* in_sizes, int n_in,
                              void* d_out, int out_size)
{
    (void)in_sizes; (void)n_in; (void)out_size;
    const float* x  = (const float*)d_in[0];
    const float* w1 = (const float*)d_in[1];
    const float* b1 = (const float*)d_in[2];
    const float* w2 = (const float*)d_in[3];
    const float* b2 = (const float*)d_in[4];
    const float* w3 = (const float*)d_in[5];
    const float* b3 = (const float*)d_in[6];
    const float* w4 = (const float*)d_in[7];
    const float* b4 = (const float*)d_in[8];
    float* out = (float*)d_out;

    // idempotent; needed for ~99 KB dynamic smem (first call outside capture)
    cudaFuncSetAttribute(attn_kernel, cudaFuncAttributeMaxDynamicSharedMemorySize,
                         SMEM_BYTES);

    conv_qkv_kernel<<<dim3(32, 4, 6), 128>>>(x, w1, b1, w2, b2, w3, b3);
    attn_kernel<<<dim3(NPIX / TM, NSPLIT), 256, SMEM_BYTES>>>();
    conv_out_kernel<<<dim3(64, 4), 64>>>(w4, b4, out);
}